// round 5
// baseline (speedup 1.0000x reference)
#include <cuda_runtime.h>

#define NB 8
#define NG 64
#define HH 256
#define HW 65536
#define NO 256
#define EPSBN 1e-5f

// per-(b,g): {coef0, coef1, coef2, bias1} with bn1 scale folded in
__device__ float g_coef[NB * NG * 4];

__device__ __forceinline__ unsigned long long packf2(float v) {
    unsigned long long r;
    asm("mov.b64 %0, {%1, %1};" : "=l"(r) : "f"(v));
    return r;
}
__device__ __forceinline__ unsigned long long pack2(float lo, float hi) {
    unsigned long long r;
    asm("mov.b64 %0, {%1, %2};" : "=l"(r) : "f"(lo), "f"(hi));
    return r;
}
__device__ __forceinline__ unsigned long long ffma2(unsigned long long a,
                                                    unsigned long long b,
                                                    unsigned long long c) {
    unsigned long long d;
    asm("fma.rn.f32x2 %0, %1, %2, %3;" : "=l"(d) : "l"(a), "l"(b), "l"(c));
    return d;
}
__device__ __forceinline__ float f2lo(unsigned long long a) {
    return __uint_as_float((unsigned)(a & 0xffffffffull));
}
__device__ __forceinline__ float f2hi(unsigned long long a) {
    return __uint_as_float((unsigned)(a >> 32));
}

// ---------------------------------------------------------------------------
// Kernel 1: per (b,g) attention weights.
//   qk[i][j] = sum over 4096 pooled windows of maxpool(x_i) * avgpool(x_j)
//   t[j] = (sum_i qk[i][j] * attnconv_w[g][i]) * (4/H)
//   a = softmax(t);  coef_j = bn1scale_g * a_j;  bias = beta1 - scale*mean1
// ---------------------------------------------------------------------------
__global__ __launch_bounds__(256) void attn_kernel(
    const float* __restrict__ x,
    const float* __restrict__ attnconv_w,
    const float* __restrict__ bn1_gamma,
    const float* __restrict__ bn1_beta,
    const float* __restrict__ bn1_mean,
    const float* __restrict__ bn1_var) {
    int bg = blockIdx.x;            // b*64 + g
    int g  = bg & 63;
    const float* xb = x + (size_t)bg * 3 * HW;   // (b*192 + g*3) * HW

    float qk[9];
#pragma unroll
    for (int i = 0; i < 9; i++) qk[i] = 0.f;

    for (int w = threadIdx.x; w < 4096; w += blockDim.x) {
        int wy = w >> 6, wx = w & 63;
        float mx[3], av[3];
#pragma unroll
        for (int j = 0; j < 3; j++) {
            const float4* row = (const float4*)(xb + (size_t)j * HW) + wy * 256 + wx;
            float4 r0 = row[0];
            float4 r1 = row[64];
            float4 r2 = row[128];
            float4 r3 = row[192];
            float s = (r0.x + r0.y + r0.z + r0.w) + (r1.x + r1.y + r1.z + r1.w)
                    + (r2.x + r2.y + r2.z + r2.w) + (r3.x + r3.y + r3.z + r3.w);
            float m = fmaxf(fmaxf(fmaxf(r0.x, r0.y), fmaxf(r0.z, r0.w)),
                     fmaxf(fmaxf(fmaxf(r1.x, r1.y), fmaxf(r1.z, r1.w)),
                     fmaxf(fmaxf(fmaxf(r2.x, r2.y), fmaxf(r2.z, r2.w)),
                           fmaxf(fmaxf(r3.x, r3.y), fmaxf(r3.z, r3.w)))));
            mx[j] = m;
            av[j] = s * (1.f / 16.f);
        }
#pragma unroll
        for (int i = 0; i < 3; i++)
#pragma unroll
            for (int j = 0; j < 3; j++)
                qk[i * 3 + j] += mx[i] * av[j];
    }

    __shared__ float red[8][9];
    int lane = threadIdx.x & 31, warp = threadIdx.x >> 5;
#pragma unroll
    for (int i = 0; i < 9; i++) {
        float v = qk[i];
#pragma unroll
        for (int o = 16; o > 0; o >>= 1) v += __shfl_down_sync(0xffffffffu, v, o);
        if (lane == 0) red[warp][i] = v;
    }
    __syncthreads();

    if (threadIdx.x == 0) {
        float q9[9];
#pragma unroll
        for (int i = 0; i < 9; i++) {
            float s = 0.f;
#pragma unroll
            for (int w8 = 0; w8 < 8; w8++) s += red[w8][i];
            q9[i] = s;
        }
        float w0 = attnconv_w[g * 3 + 0];
        float w1 = attnconv_w[g * 3 + 1];
        float w2 = attnconv_w[g * 3 + 2];
        float t[3];
#pragma unroll
        for (int j = 0; j < 3; j++)
            t[j] = (q9[j] * w0 + q9[3 + j] * w1 + q9[6 + j] * w2) * (4.0f / HH);
        float m = fmaxf(t[0], fmaxf(t[1], t[2]));
        float e0 = expf(t[0] - m), e1 = expf(t[1] - m), e2 = expf(t[2] - m);
        float inv = 1.f / (e0 + e1 + e2);
        float s1 = bn1_gamma[g] * rsqrtf(bn1_var[g] + EPSBN);
        float* cp = &g_coef[bg * 4];
        cp[0] = e0 * inv * s1;
        cp[1] = e1 * inv * s1;
        cp[2] = e2 * inv * s1;
        cp[3] = bn1_beta[g] - s1 * bn1_mean[g];
    }
}

// ---------------------------------------------------------------------------
// Kernel 2: fused V-build + 256x64 GEMM + BN2.
//   V[g][n] = relu(c0*x[3g] + c1*x[3g+1] + c2*x[3g+2] + bias1)   (on the fly)
//   out[o][n] = (bn2scale_o * W[o][:]) @ V[:][n] + bias2_o
// Tile: M=256 (all outputs), N=128 pixels, K=64.
// Thread (to = tid/8 in [0,32), tn = tid%8): 8 outputs x 16 pixels,
// pixels n = tn*4 + m*32 (m=0..3) -> conflict-free LDS.128 / coalesced STG.
// ---------------------------------------------------------------------------
__global__ __launch_bounds__(256, 1) void fused_gemm_kernel(
    const float* __restrict__ x,
    const float* __restrict__ conv_w,
    const float* __restrict__ bn2_gamma,
    const float* __restrict__ bn2_beta,
    const float* __restrict__ bn2_mean,
    const float* __restrict__ bn2_var,
    float* __restrict__ out) {
    extern __shared__ float smem[];
    float* Wsh = smem;               // [64][256]  k-major
    float* Vsh = smem + 64 * 256;    // [64][128]
    float* bsh = Vsh + 64 * 128;     // [256]

    int b   = blockIdx.y;
    int n0  = blockIdx.x * 128;
    int tid = threadIdx.x;

    // Stage W folded with bn2 scale (k-major), and bn2 bias.
    {
        float s2 = bn2_gamma[tid] * rsqrtf(bn2_var[tid] + EPSBN);
        bsh[tid] = bn2_beta[tid] - s2 * bn2_mean[tid];
#pragma unroll
        for (int r = 0; r < 64; r += 4) {
            // thread handles o = tid for 64 k values: coalesce over o instead:
            // i = tid + (r/4)*1024... simpler: strided fill below
        }
    }
    for (int i = tid; i < 64 * 256; i += 256) {
        int k = i >> 8, o = i & 255;
        float s2 = bn2_gamma[o] * rsqrtf(bn2_var[o] + EPSBN);
        Wsh[i] = conv_w[o * 64 + k] * s2;
    }

    // Build V tile: 64 groups x 128 pixels, float4 granularity.
    for (int i = tid; i < 64 * 32; i += 256) {
        int g = i >> 5, nv = i & 31;
        const float* cp = &g_coef[(b * 64 + g) * 4];
        float c0 = cp[0], c1 = cp[1], c2 = cp[2], bias = cp[3];
        size_t base = ((size_t)(b * 192 + g * 3)) * HW + n0 + nv * 4;
        float4 x0 = *(const float4*)(x + base);
        float4 x1 = *(const float4*)(x + base + HW);
        float4 x2 = *(const float4*)(x + base + 2 * HW);
        float4 v;
        v.x = fmaxf(fmaf(c0, x0.x, fmaf(c1, x1.x, fmaf(c2, x2.x, bias))), 0.f);
        v.y = fmaxf(fmaf(c0, x0.y, fmaf(c1, x1.y, fmaf(c2, x2.y, bias))), 0.f);
        v.z = fmaxf(fmaf(c0, x0.z, fmaf(c1, x1.z, fmaf(c2, x2.z, bias))), 0.f);
        v.w = fmaxf(fmaf(c0, x0.w, fmaf(c1, x1.w, fmaf(c2, x2.w, bias))), 0.f);
        *(float4*)(Vsh + g * 128 + nv * 4) = v;
    }
    __syncthreads();

    int tn = tid & 7;         // pixel group
    int to = tid >> 3;        // output group
    int o0 = to * 8;

    unsigned long long acc[8][8];
#pragma unroll
    for (int j = 0; j < 8; j++)
#pragma unroll
        for (int p = 0; p < 8; p++) acc[j][p] = 0ull;

#pragma unroll 2
    for (int k = 0; k < 64; k++) {
        float4 wa = *(const float4*)(Wsh + k * 256 + o0);
        float4 wb = *(const float4*)(Wsh + k * 256 + o0 + 4);
        unsigned long long wp[8];
        wp[0] = packf2(wa.x); wp[1] = packf2(wa.y);
        wp[2] = packf2(wa.z); wp[3] = packf2(wa.w);
        wp[4] = packf2(wb.x); wp[5] = packf2(wb.y);
        wp[6] = packf2(wb.z); wp[7] = packf2(wb.w);
        unsigned long long vp[8];
#pragma unroll
        for (int m = 0; m < 4; m++) {
            float4 vv = *(const float4*)(Vsh + k * 128 + tn * 4 + m * 32);
            vp[2 * m]     = pack2(vv.x, vv.y);
            vp[2 * m + 1] = pack2(vv.z, vv.w);
        }
#pragma unroll
        for (int j = 0; j < 8; j++)
#pragma unroll
            for (int p = 0; p < 8; p++)
                acc[j][p] = ffma2(wp[j], vp[p], acc[j][p]);
    }

    // Epilogue: add bn2 bias, store coalesced.
#pragma unroll
    for (int j = 0; j < 8; j++) {
        int o = o0 + j;
        float bias2 = bsh[o];
        float* orow = out + ((size_t)(b * NO + o)) * HW + n0;
#pragma unroll
        for (int m = 0; m < 4; m++) {
            unsigned long long a0 = acc[j][2 * m];
            unsigned long long a1 = acc[j][2 * m + 1];
            float4 r;
            r.x = f2lo(a0) + bias2;
            r.y = f2hi(a0) + bias2;
            r.z = f2lo(a1) + bias2;
            r.w = f2hi(a1) + bias2;
            *(float4*)(orow + tn * 4 + m * 32) = r;
        }
    }
}

extern "C" void kernel_launch(void* const* d_in, const int* in_sizes, int n_in,
                              void* d_out, int out_size) {
    const float* x          = (const float*)d_in[0];
    const float* attnconv_w = (const float*)d_in[1];
    const float* bn1_gamma  = (const float*)d_in[2];
    const float* bn1_beta   = (const float*)d_in[3];
    const float* bn1_mean   = (const float*)d_in[4];
    const float* bn1_var    = (const float*)d_in[5];
    const float* conv_w     = (const float*)d_in[6];
    const float* bn2_gamma  = (const float*)d_in[7];
    const float* bn2_beta   = (const float*)d_in[8];
    const float* bn2_mean   = (const float*)d_in[9];
    const float* bn2_var    = (const float*)d_in[10];
    float* out = (float*)d_out;

    attn_kernel<<<NB * NG, 256>>>(x, attnconv_w, bn1_gamma, bn1_beta,
                                  bn1_mean, bn1_var);

    size_t smem_bytes = (64 * 256 + 64 * 128 + 256) * sizeof(float); // 99328
    cudaFuncSetAttribute(fused_gemm_kernel,
                         cudaFuncAttributeMaxDynamicSharedMemorySize,
                         (int)smem_bytes);
    dim3 grid(HW / 128, NB);
    fused_gemm_kernel<<<grid, 256, smem_bytes>>>(x, conv_w, bn2_gamma, bn2_beta,
                                                 bn2_mean, bn2_var, out);
}

// round 7
// speedup vs baseline: 1.0557x; 1.0557x over previous
#include <cuda_runtime.h>

#define NB 8
#define NG 64
#define HH 256
#define HW 65536
#define NO 256
#define EPSBN 1e-5f

// per-(b,g): {coef0, coef1, coef2, bias1} with bn1 scale folded in
__device__ float g_coef[NB * NG * 4];

__device__ __forceinline__ unsigned long long packf2(float v) {
    unsigned long long r;
    asm("mov.b64 %0, {%1, %1};" : "=l"(r) : "f"(v));
    return r;
}
__device__ __forceinline__ unsigned long long pack2(float lo, float hi) {
    unsigned long long r;
    asm("mov.b64 %0, {%1, %2};" : "=l"(r) : "f"(lo), "f"(hi));
    return r;
}
__device__ __forceinline__ unsigned long long ffma2(unsigned long long a,
                                                    unsigned long long b,
                                                    unsigned long long c) {
    unsigned long long d;
    asm("fma.rn.f32x2 %0, %1, %2, %3;" : "=l"(d) : "l"(a), "l"(b), "l"(c));
    return d;
}
__device__ __forceinline__ float f2lo(unsigned long long a) {
    return __uint_as_float((unsigned)(a & 0xffffffffull));
}
__device__ __forceinline__ float f2hi(unsigned long long a) {
    return __uint_as_float((unsigned)(a >> 32));
}

// ---------------------------------------------------------------------------
// Kernel 1: per (b,g) attention weights.
//   qk[i][j] = sum over 4096 pooled windows of maxpool(x_i) * avgpool(x_j)
//   t[j] = (sum_i qk[i][j] * attnconv_w[g][i]) * (4/H)
//   a = softmax(t);  coef_j = bn1scale_g * a_j;  bias = beta1 - scale*mean1
// ---------------------------------------------------------------------------
__global__ __launch_bounds__(256) void attn_kernel(
    const float* __restrict__ x,
    const float* __restrict__ attnconv_w,
    const float* __restrict__ bn1_gamma,
    const float* __restrict__ bn1_beta,
    const float* __restrict__ bn1_mean,
    const float* __restrict__ bn1_var) {
    int bg = blockIdx.x;            // b*64 + g
    int g  = bg & 63;
    const float* xb = x + (size_t)bg * 3 * HW;   // (b*192 + g*3) * HW

    float qk[9];
#pragma unroll
    for (int i = 0; i < 9; i++) qk[i] = 0.f;

    for (int w = threadIdx.x; w < 4096; w += blockDim.x) {
        int wy = w >> 6, wx = w & 63;
        float mx[3], av[3];
#pragma unroll
        for (int j = 0; j < 3; j++) {
            const float4* row = (const float4*)(xb + (size_t)j * HW) + wy * 256 + wx;
            float4 r0 = row[0];
            float4 r1 = row[64];
            float4 r2 = row[128];
            float4 r3 = row[192];
            float s = (r0.x + r0.y + r0.z + r0.w) + (r1.x + r1.y + r1.z + r1.w)
                    + (r2.x + r2.y + r2.z + r2.w) + (r3.x + r3.y + r3.z + r3.w);
            float m = fmaxf(fmaxf(fmaxf(r0.x, r0.y), fmaxf(r0.z, r0.w)),
                     fmaxf(fmaxf(fmaxf(r1.x, r1.y), fmaxf(r1.z, r1.w)),
                     fmaxf(fmaxf(fmaxf(r2.x, r2.y), fmaxf(r2.z, r2.w)),
                           fmaxf(fmaxf(r3.x, r3.y), fmaxf(r3.z, r3.w)))));
            mx[j] = m;
            av[j] = s * (1.f / 16.f);
        }
#pragma unroll
        for (int i = 0; i < 3; i++)
#pragma unroll
            for (int j = 0; j < 3; j++)
                qk[i * 3 + j] += mx[i] * av[j];
    }

    __shared__ float red[8][9];
    int lane = threadIdx.x & 31, warp = threadIdx.x >> 5;
#pragma unroll
    for (int i = 0; i < 9; i++) {
        float v = qk[i];
#pragma unroll
        for (int o = 16; o > 0; o >>= 1) v += __shfl_down_sync(0xffffffffu, v, o);
        if (lane == 0) red[warp][i] = v;
    }
    __syncthreads();

    if (threadIdx.x == 0) {
        float q9[9];
#pragma unroll
        for (int i = 0; i < 9; i++) {
            float s = 0.f;
#pragma unroll
            for (int w8 = 0; w8 < 8; w8++) s += red[w8][i];
            q9[i] = s;
        }
        float w0 = attnconv_w[g * 3 + 0];
        float w1 = attnconv_w[g * 3 + 1];
        float w2 = attnconv_w[g * 3 + 2];
        float t[3];
#pragma unroll
        for (int j = 0; j < 3; j++)
            t[j] = (q9[j] * w0 + q9[3 + j] * w1 + q9[6 + j] * w2) * (4.0f / HH);
        float m = fmaxf(t[0], fmaxf(t[1], t[2]));
        float e0 = expf(t[0] - m), e1 = expf(t[1] - m), e2 = expf(t[2] - m);
        float inv = 1.f / (e0 + e1 + e2);
        float s1 = bn1_gamma[g] * rsqrtf(bn1_var[g] + EPSBN);
        float* cp = &g_coef[bg * 4];
        cp[0] = e0 * inv * s1;
        cp[1] = e1 * inv * s1;
        cp[2] = e2 * inv * s1;
        cp[3] = bn1_beta[g] - s1 * bn1_mean[g];
    }
}

// ---------------------------------------------------------------------------
// Kernel 2: fused V-build + 256x64 GEMM + BN2.
// Tile: M=256 (all outputs), N=128 pixels, K=64.  512 threads.
// Thread (to = tid>>4 in [0,32), tn = tid&15): 8 outputs x 8 pixels,
// pixels n = tn*4 + m*64 (m=0,1) -> broadcast LDS.128, coalesced STG.
// 32 u64 accumulators (64 regs) -> ~110 regs/thread -> 16 warps resident.
// ---------------------------------------------------------------------------
__global__ __launch_bounds__(512, 1) void fused_gemm_kernel(
    const float* __restrict__ x,
    const float* __restrict__ conv_w,
    const float* __restrict__ bn2_gamma,
    const float* __restrict__ bn2_beta,
    const float* __restrict__ bn2_mean,
    const float* __restrict__ bn2_var,
    float* __restrict__ out) {
    extern __shared__ float smem[];
    float* Wsh = smem;               // [64][256]  k-major
    float* Vsh = smem + 64 * 256;    // [64][128]
    float* bsh = Vsh + 64 * 128;     // [256] bn2 bias
    float* ssh = bsh + 256;          // [256] bn2 scale

    int b   = blockIdx.y;
    int n0  = blockIdx.x * 128;
    int tid = threadIdx.x;

    if (tid < 256) {
        float s2 = bn2_gamma[tid] * rsqrtf(bn2_var[tid] + EPSBN);
        ssh[tid] = s2;
        bsh[tid] = bn2_beta[tid] - s2 * bn2_mean[tid];
    }
    __syncthreads();

    // Stage W folded with bn2 scale (k-major).
    for (int i = tid; i < 64 * 256; i += 512) {
        int k = i >> 8, o = i & 255;
        Wsh[i] = conv_w[o * 64 + k] * ssh[o];
    }

    // Build V tile: 64 groups x 128 pixels, float4 granularity.
    for (int i = tid; i < 64 * 32; i += 512) {
        int g = i >> 5, nv = i & 31;
        const float* cp = &g_coef[(b * 64 + g) * 4];
        float c0 = cp[0], c1 = cp[1], c2 = cp[2], bias = cp[3];
        size_t base = ((size_t)(b * 192 + g * 3)) * HW + n0 + nv * 4;
        float4 x0 = *(const float4*)(x + base);
        float4 x1 = *(const float4*)(x + base + HW);
        float4 x2 = *(const float4*)(x + base + 2 * HW);
        float4 v;
        v.x = fmaxf(fmaf(c0, x0.x, fmaf(c1, x1.x, fmaf(c2, x2.x, bias))), 0.f);
        v.y = fmaxf(fmaf(c0, x0.y, fmaf(c1, x1.y, fmaf(c2, x2.y, bias))), 0.f);
        v.z = fmaxf(fmaf(c0, x0.z, fmaf(c1, x1.z, fmaf(c2, x2.z, bias))), 0.f);
        v.w = fmaxf(fmaf(c0, x0.w, fmaf(c1, x1.w, fmaf(c2, x2.w, bias))), 0.f);
        *(float4*)(Vsh + g * 128 + nv * 4) = v;
    }
    __syncthreads();

    int tn = tid & 15;        // pixel group  (n = tn*4 + m*64)
    int to = tid >> 4;        // output group (o = to*8 + j)
    int o0 = to * 8;

    unsigned long long acc[8][4];
#pragma unroll
    for (int j = 0; j < 8; j++)
#pragma unroll
        for (int p = 0; p < 4; p++) acc[j][p] = 0ull;

#pragma unroll 4
    for (int k = 0; k < 64; k++) {
        float4 wa = *(const float4*)(Wsh + k * 256 + o0);
        float4 wb = *(const float4*)(Wsh + k * 256 + o0 + 4);
        unsigned long long wp[8];
        wp[0] = packf2(wa.x); wp[1] = packf2(wa.y);
        wp[2] = packf2(wa.z); wp[3] = packf2(wa.w);
        wp[4] = packf2(wb.x); wp[5] = packf2(wb.y);
        wp[6] = packf2(wb.z); wp[7] = packf2(wb.w);
        unsigned long long vp[4];
#pragma unroll
        for (int m = 0; m < 2; m++) {
            float4 vv = *(const float4*)(Vsh + k * 128 + tn * 4 + m * 64);
            vp[2 * m]     = pack2(vv.x, vv.y);
            vp[2 * m + 1] = pack2(vv.z, vv.w);
        }
#pragma unroll
        for (int j = 0; j < 8; j++)
#pragma unroll
            for (int p = 0; p < 4; p++)
                acc[j][p] = ffma2(wp[j], vp[p], acc[j][p]);
    }

    // Epilogue: add bn2 bias, store coalesced (16 threads x 16B = 256B runs).
#pragma unroll
    for (int j = 0; j < 8; j++) {
        int o = o0 + j;
        float bias2 = bsh[o];
        float* orow = out + ((size_t)(b * NO + o)) * HW + n0;
#pragma unroll
        for (int m = 0; m < 2; m++) {
            unsigned long long a0 = acc[j][2 * m];
            unsigned long long a1 = acc[j][2 * m + 1];
            float4 r;
            r.x = f2lo(a0) + bias2;
            r.y = f2hi(a0) + bias2;
            r.z = f2lo(a1) + bias2;
            r.w = f2hi(a1) + bias2;
            *(float4*)(orow + tn * 4 + m * 64) = r;
        }
    }
}

extern "C" void kernel_launch(void* const* d_in, const int* in_sizes, int n_in,
                              void* d_out, int out_size) {
    const float* x          = (const float*)d_in[0];
    const float* attnconv_w = (const float*)d_in[1];
    const float* bn1_gamma  = (const float*)d_in[2];
    const float* bn1_beta   = (const float*)d_in[3];
    const float* bn1_mean   = (const float*)d_in[4];
    const float* bn1_var    = (const float*)d_in[5];
    const float* conv_w     = (const float*)d_in[6];
    const float* bn2_gamma  = (const float*)d_in[7];
    const float* bn2_beta   = (const float*)d_in[8];
    const float* bn2_mean   = (const float*)d_in[9];
    const float* bn2_var    = (const float*)d_in[10];
    float* out = (float*)d_out;

    attn_kernel<<<NB * NG, 256>>>(x, attnconv_w, bn1_gamma, bn1_beta,
                                  bn1_mean, bn1_var);

    size_t smem_bytes = (64 * 256 + 64 * 128 + 256 + 256) * sizeof(float); // 100352
    cudaFuncSetAttribute(fused_gemm_kernel,
                         cudaFuncAttributeMaxDynamicSharedMemorySize,
                         (int)smem_bytes);
    dim3 grid(HW / 128, NB);
    fused_gemm_kernel<<<grid, 512, smem_bytes>>>(x, conv_w, bn2_gamma, bn2_beta,
                                                 bn2_mean, bn2_var, out);
}